// round 14
// baseline (speedup 1.0000x reference)
#include <cuda_runtime.h>
#include <math.h>

// Problem constants
#define BB   8
#define TT   2048
#define DD   512
#define TD   ((long)TT * DD)       // 1,048,576
#define TXT  ((long)TT * TT)       // 4,194,304
#define SCALE 0.044194173824159216f // 1/sqrt(512)

// ---------------- scratch (static device globals; no runtime allocation) ---
__device__ __align__(128) float g_E[BB * TT * DD];
__device__ __align__(128) float g_Q[BB * TT * DD];
__device__ __align__(128) float g_K[BB * TT * DD];
__device__ __align__(128) float g_V[BB * TT * DD];
__device__ __align__(128) float g_S[(long)BB * TT * TT];
__device__ __align__(128) float g_Y[BB * TT * DD];
__device__ __align__(128) float g_Z[BB * TT * DD];
__device__ __align__(128) float g_Mp[8 * BB * DD];   // [split][b][o]

// ---------------- embedding gather --------------------------------------
__global__ void embed_kernel(const int* __restrict__ x,
                             const float* __restrict__ W,
                             float* __restrict__ E) {
    long i = (long)blockIdx.x * blockDim.x + threadIdx.x;  // float4 units
    int  d4 = (int)(i & 127);            // D/4 = 128
    long bt = i >> 7;
    int tok = __ldg(&x[bt]);
    ((float4*)E)[i] = ((const float4*)W)[(long)tok * 128 + d4];
}

// ---------------- SGEMM: C = alpha * A * op(B) ---------------------------
// A: M x K row-major.  TRANSB: B is N x K row-major (C=A*B^T), else K x N.
// 128x128 block tile, BK=8, 256 threads, 8x8 per-thread microtile,
// one-step register prefetch of the next global tile.
template <bool TRANSB>
__global__ void __launch_bounds__(256)
sgemm_kernel(const float* __restrict__ A, const float* __restrict__ Bm,
             float* __restrict__ C, int M, int N, int K,
             long sA, long sB, long sC, float alpha) {
    __shared__ float As[8][128];
    __shared__ float Bs[8][128];

    const int bz = blockIdx.z;
    A  += (long)bz * sA;
    Bm += (long)bz * sB;
    C  += (long)bz * sC;

    const int m0 = blockIdx.y * 128;
    const int n0 = blockIdx.x * 128;
    const int tid = threadIdx.x;
    const int tx = tid & 15;        // 0..15 -> n microtile
    const int ty = tid >> 4;        // 0..15 -> m microtile

    // A / (NT) B loader indices: one float4 per thread, 128 rows x 8 cols
    const int lrow = tid >> 1;            // 0..127
    const int lcol = (tid & 1) << 2;      // 0 or 4
    // (NN) B loader indices: 8 rows x 128 cols, coalesced
    const int brow = tid >> 5;            // 0..7
    const int bcol = (tid & 31) << 2;     // 0..124

    const float* Aptr = A + (long)(m0 + lrow) * K + lcol;
    const float* Bptr = TRANSB ? (Bm + (long)(n0 + lrow) * K + lcol)
                               : (Bm + (long)brow * N + n0 + bcol);

    float acc[8][8];
#pragma unroll
    for (int i = 0; i < 8; i++)
#pragma unroll
        for (int j = 0; j < 8; j++) acc[i][j] = 0.f;

    // prime the pipeline
    float4 av = *(const float4*)(Aptr);
    float4 bv = TRANSB ? *(const float4*)(Bptr)
                       : *(const float4*)(Bptr);

    for (int k0 = 0; k0 < K; k0 += 8) {
        // stage current tile to smem
        As[lcol + 0][lrow] = av.x;
        As[lcol + 1][lrow] = av.y;
        As[lcol + 2][lrow] = av.z;
        As[lcol + 3][lrow] = av.w;
        if (TRANSB) {
            Bs[lcol + 0][lrow] = bv.x;
            Bs[lcol + 1][lrow] = bv.y;
            Bs[lcol + 2][lrow] = bv.z;
            Bs[lcol + 3][lrow] = bv.w;
        } else {
            *(float4*)&Bs[brow][bcol] = bv;
        }
        __syncthreads();

        // prefetch next global tile (hidden under compute)
        float4 av_n = make_float4(0.f, 0.f, 0.f, 0.f);
        float4 bv_n = make_float4(0.f, 0.f, 0.f, 0.f);
        if (k0 + 8 < K) {
            av_n = *(const float4*)(Aptr + k0 + 8);
            bv_n = TRANSB ? *(const float4*)(Bptr + k0 + 8)
                          : *(const float4*)(Bptr + (long)(k0 + 8) * N);
        }

#pragma unroll
        for (int kk = 0; kk < 8; kk++) {
            float a[8], b[8];
            *(float4*)&a[0] = *(const float4*)&As[kk][ty * 8];
            *(float4*)&a[4] = *(const float4*)&As[kk][ty * 8 + 4];
            *(float4*)&b[0] = *(const float4*)&Bs[kk][tx * 8];
            *(float4*)&b[4] = *(const float4*)&Bs[kk][tx * 8 + 4];
#pragma unroll
            for (int i = 0; i < 8; i++)
#pragma unroll
                for (int j = 0; j < 8; j++)
                    acc[i][j] = fmaf(a[i], b[j], acc[i][j]);
        }
        __syncthreads();
        av = av_n;
        bv = bv_n;
    }

#pragma unroll
    for (int i = 0; i < 8; i++) {
        float* crow = C + (long)(m0 + ty * 8 + i) * N + n0 + tx * 8;
        float4 c0 = make_float4(acc[i][0] * alpha, acc[i][1] * alpha,
                                acc[i][2] * alpha, acc[i][3] * alpha);
        float4 c1 = make_float4(acc[i][4] * alpha, acc[i][5] * alpha,
                                acc[i][6] * alpha, acc[i][7] * alpha);
        *(float4*)crow       = c0;
        *(float4*)(crow + 4) = c1;
    }
}

// ---------------- row softmax over T=2048 --------------------------------
__global__ void softmax_kernel(float* __restrict__ S) {
    __shared__ float redmax[8];
    __shared__ float redsum[8];
    long row = blockIdx.x;
    float4* p4 = (float4*)(S + row * (long)TT);
    int t = threadIdx.x;                    // 256 threads, 8 floats each
    float4 v0 = p4[t];
    float4 v1 = p4[t + 256];

    float m = fmaxf(fmaxf(fmaxf(v0.x, v0.y), fmaxf(v0.z, v0.w)),
                    fmaxf(fmaxf(v1.x, v1.y), fmaxf(v1.z, v1.w)));
#pragma unroll
    for (int o = 16; o > 0; o >>= 1) m = fmaxf(m, __shfl_xor_sync(0xffffffffu, m, o));
    if ((t & 31) == 0) redmax[t >> 5] = m;
    __syncthreads();
    float rm = redmax[0];
#pragma unroll
    for (int w = 1; w < 8; w++) rm = fmaxf(rm, redmax[w]);

    v0.x = __expf(v0.x - rm); v0.y = __expf(v0.y - rm);
    v0.z = __expf(v0.z - rm); v0.w = __expf(v0.w - rm);
    v1.x = __expf(v1.x - rm); v1.y = __expf(v1.y - rm);
    v1.z = __expf(v1.z - rm); v1.w = __expf(v1.w - rm);

    float s = (v0.x + v0.y) + (v0.z + v0.w) + (v1.x + v1.y) + (v1.z + v1.w);
#pragma unroll
    for (int o = 16; o > 0; o >>= 1) s += __shfl_xor_sync(0xffffffffu, s, o);
    if ((t & 31) == 0) redsum[t >> 5] = s;
    __syncthreads();
    float tot = 0.f;
#pragma unroll
    for (int w = 0; w < 8; w++) tot += redsum[w];
    float inv = 1.0f / tot;

    v0.x *= inv; v0.y *= inv; v0.z *= inv; v0.w *= inv;
    v1.x *= inv; v1.y *= inv; v1.z *= inv; v1.w *= inv;
    p4[t]       = v0;
    p4[t + 256] = v1;
}

// ---------------- bias + relu + partial mean over time -------------------
// grid (D/128, B, 8 splits), 128 threads; each thread owns one output dim.
__global__ void relu_mean_kernel(const float* __restrict__ Z,
                                 const float* __restrict__ bias,
                                 float* __restrict__ Mp) {
    int o  = blockIdx.x * 128 + threadIdx.x;
    int b  = blockIdx.y;
    int sp = blockIdx.z;
    float bo = bias[o];
    const float* p = Z + ((long)b * TT + (long)sp * 256) * DD + o;
    float s = 0.f;
#pragma unroll 8
    for (int i = 0; i < 256; i++) s += fmaxf(p[(long)i * DD] + bo, 0.f);
    Mp[((long)sp * BB + b) * DD + o] = s;
}

// ---------------- classifier: sigmoid(mean . clf_w + clf_b) --------------
__global__ void final_kernel(const float* __restrict__ Mp,
                             const float* __restrict__ clf_w,
                             const float* __restrict__ clf_b,
                             float* __restrict__ out) {
    int b    = threadIdx.x >> 5;   // 8 warps, one per batch row
    int lane = threadIdx.x & 31;
    float s = 0.f;
    for (int o = lane; o < DD; o += 32) {
        float m = 0.f;
#pragma unroll
        for (int sp = 0; sp < 8; sp++) m += Mp[((long)sp * BB + b) * DD + o];
        s += (m * (1.0f / (float)TT)) * clf_w[o];
    }
#pragma unroll
    for (int o = 16; o > 0; o >>= 1) s += __shfl_xor_sync(0xffffffffu, s, o);
    if (lane == 0) out[b] = 1.0f / (1.0f + __expf(-(s + clf_b[0])));
}

// ---------------- launch ---------------------------------------------------
extern "C" void kernel_launch(void* const* d_in, const int* in_sizes, int n_in,
                              void* d_out, int out_size) {
    const int*   x     = (const int*)  d_in[0];
    const float* embed = (const float*)d_in[1];
    const float* W_q   = (const float*)d_in[2];
    const float* W_k   = (const float*)d_in[3];
    const float* W_v   = (const float*)d_in[4];
    const float* lin_w = (const float*)d_in[5];
    const float* lin_b = (const float*)d_in[6];
    const float* clf_w = (const float*)d_in[7];
    const float* clf_b = (const float*)d_in[8];
    float* out = (float*)d_out;

    float *E, *Q, *K, *V, *S, *Y, *Z, *Mp;
    cudaGetSymbolAddress((void**)&E,  g_E);
    cudaGetSymbolAddress((void**)&Q,  g_Q);
    cudaGetSymbolAddress((void**)&K,  g_K);
    cudaGetSymbolAddress((void**)&V,  g_V);
    cudaGetSymbolAddress((void**)&S,  g_S);
    cudaGetSymbolAddress((void**)&Y,  g_Y);
    cudaGetSymbolAddress((void**)&Z,  g_Z);
    cudaGetSymbolAddress((void**)&Mp, g_Mp);

    // 1) E[b,t,:] = embed[x[b,t],:]
    embed_kernel<<<(BB * TT * (DD / 4)) / 256, 256>>>(x, embed, E);

    // 2) Q/K/V[b,t,d] = sum_f E[b,t,f] * W[d,f]   (NT GEMM)
    dim3 gqkv(DD / 128, TT / 128, BB);
    sgemm_kernel<true><<<gqkv, 256>>>(E, W_q, Q, TT, DD, DD, TD, 0, TD, 1.0f);
    sgemm_kernel<true><<<gqkv, 256>>>(E, W_k, K, TT, DD, DD, TD, 0, TD, 1.0f);
    sgemm_kernel<true><<<gqkv, 256>>>(E, W_v, V, TT, DD, DD, TD, 0, TD, 1.0f);

    // 3) S[b,i,j] = SCALE * Q[b,i,:].K[b,j,:]     (NT GEMM)
    dim3 gsc(TT / 128, TT / 128, BB);
    sgemm_kernel<true><<<gsc, 256>>>(Q, K, S, TT, TT, DD, TD, TD, TXT, SCALE);

    // 4) softmax over j
    softmax_kernel<<<BB * TT, 256>>>(S);

    // 5) Y[b,i,d] = sum_j S[b,i,j] * V[b,j,d]     (NN GEMM)
    dim3 gav(DD / 128, TT / 128, BB);
    sgemm_kernel<false><<<gav, 256>>>(S, V, Y, TT, DD, TT, TXT, TD, TD, 1.0f);

    // 6) Z[b,i,o] = Y[b,i,:] . lin_w[o,:]         (NT GEMM, bias in step 7)
    sgemm_kernel<true><<<gav, 256>>>(Y, lin_w, Z, TT, DD, DD, TD, 0, TD, 1.0f);

    // 7) partial mean of relu(Z + b) over time
    relu_mean_kernel<<<dim3(DD / 128, BB, 8), 128>>>(Z, lin_b, Mp);

    // 8) sigmoid classifier
    final_kernel<<<1, 256>>>(Mp, clf_w, clf_b, out);
}

// round 15
// speedup vs baseline: 1.0495x; 1.0495x over previous
#include <cuda_runtime.h>
#include <math.h>

// Problem constants
#define BB   8
#define TT   2048
#define DD   512
#define TD   ((long)TT * DD)       // 1,048,576
#define TXT  ((long)TT * TT)       // 4,194,304
#define SCALE 0.044194173824159216f // 1/sqrt(512)

// ---------------- scratch (static device globals; no runtime allocation) ---
__device__ __align__(128) float g_E[BB * TT * DD];
__device__ __align__(128) float g_Q[BB * TT * DD];
__device__ __align__(128) float g_K[BB * TT * DD];
__device__ __align__(128) float g_V[BB * TT * DD];
__device__ __align__(128) float g_S[(long)BB * TT * TT];
__device__ __align__(128) float g_Y[BB * TT * DD];
__device__ __align__(128) float g_Z[BB * TT * DD];
__device__ __align__(128) float g_Mp[8 * BB * DD];   // [split][b][o]

// ---------------- embedding gather --------------------------------------
__global__ void embed_kernel(const int* __restrict__ x,
                             const float* __restrict__ W,
                             float* __restrict__ E) {
    long i = (long)blockIdx.x * blockDim.x + threadIdx.x;  // float4 units
    int  d4 = (int)(i & 127);            // D/4 = 128
    long bt = i >> 7;
    int tok = __ldg(&x[bt]);
    ((float4*)E)[i] = ((const float4*)W)[(long)tok * 128 + d4];
}

// ---------------- SGEMM: C = alpha * A * op(B) ---------------------------
// A: M x K row-major.  TRANSB: B is N x K row-major (C=A*B^T), else K x N.
// 128x128 block tile, BK=8, 256 threads, 8x8 per-thread microtile,
// one-step register prefetch of the next global tile.
template <bool TRANSB>
__global__ void __launch_bounds__(256)
sgemm_kernel(const float* __restrict__ A, const float* __restrict__ Bm,
             float* __restrict__ C, int M, int N, int K,
             long sA, long sB, long sC, float alpha) {
    __shared__ float As[8][128];
    __shared__ float Bs[8][128];

    const int bz = blockIdx.z;
    A  += (long)bz * sA;
    Bm += (long)bz * sB;
    C  += (long)bz * sC;

    const int m0 = blockIdx.y * 128;
    const int n0 = blockIdx.x * 128;
    const int tid = threadIdx.x;
    const int tx = tid & 15;        // 0..15 -> n microtile
    const int ty = tid >> 4;        // 0..15 -> m microtile

    // A / (NT) B loader indices: one float4 per thread, 128 rows x 8 cols
    const int lrow = tid >> 1;            // 0..127
    const int lcol = (tid & 1) << 2;      // 0 or 4
    // (NN) B loader indices: 8 rows x 128 cols, coalesced
    const int brow = tid >> 5;            // 0..7
    const int bcol = (tid & 31) << 2;     // 0..124

    const float* Aptr = A + (long)(m0 + lrow) * K + lcol;
    const float* Bptr = TRANSB ? (Bm + (long)(n0 + lrow) * K + lcol)
                               : (Bm + (long)brow * N + n0 + bcol);

    float acc[8][8];
#pragma unroll
    for (int i = 0; i < 8; i++)
#pragma unroll
        for (int j = 0; j < 8; j++) acc[i][j] = 0.f;

    // prime the pipeline
    float4 av = *(const float4*)(Aptr);
    float4 bv = TRANSB ? *(const float4*)(Bptr)
                       : *(const float4*)(Bptr);

    for (int k0 = 0; k0 < K; k0 += 8) {
        // stage current tile to smem
        As[lcol + 0][lrow] = av.x;
        As[lcol + 1][lrow] = av.y;
        As[lcol + 2][lrow] = av.z;
        As[lcol + 3][lrow] = av.w;
        if (TRANSB) {
            Bs[lcol + 0][lrow] = bv.x;
            Bs[lcol + 1][lrow] = bv.y;
            Bs[lcol + 2][lrow] = bv.z;
            Bs[lcol + 3][lrow] = bv.w;
        } else {
            *(float4*)&Bs[brow][bcol] = bv;
        }
        __syncthreads();

        // prefetch next global tile (hidden under compute)
        float4 av_n = make_float4(0.f, 0.f, 0.f, 0.f);
        float4 bv_n = make_float4(0.f, 0.f, 0.f, 0.f);
        if (k0 + 8 < K) {
            av_n = *(const float4*)(Aptr + k0 + 8);
            bv_n = TRANSB ? *(const float4*)(Bptr + k0 + 8)
                          : *(const float4*)(Bptr + (long)(k0 + 8) * N);
        }

#pragma unroll
        for (int kk = 0; kk < 8; kk++) {
            float a[8], b[8];
            *(float4*)&a[0] = *(const float4*)&As[kk][ty * 8];
            *(float4*)&a[4] = *(const float4*)&As[kk][ty * 8 + 4];
            *(float4*)&b[0] = *(const float4*)&Bs[kk][tx * 8];
            *(float4*)&b[4] = *(const float4*)&Bs[kk][tx * 8 + 4];
#pragma unroll
            for (int i = 0; i < 8; i++)
#pragma unroll
                for (int j = 0; j < 8; j++)
                    acc[i][j] = fmaf(a[i], b[j], acc[i][j]);
        }
        __syncthreads();
        av = av_n;
        bv = bv_n;
    }

#pragma unroll
    for (int i = 0; i < 8; i++) {
        float* crow = C + (long)(m0 + ty * 8 + i) * N + n0 + tx * 8;
        float4 c0 = make_float4(acc[i][0] * alpha, acc[i][1] * alpha,
                                acc[i][2] * alpha, acc[i][3] * alpha);
        float4 c1 = make_float4(acc[i][4] * alpha, acc[i][5] * alpha,
                                acc[i][6] * alpha, acc[i][7] * alpha);
        *(float4*)crow       = c0;
        *(float4*)(crow + 4) = c1;
    }
}

// ---------------- row softmax over T=2048 --------------------------------
__global__ void softmax_kernel(float* __restrict__ S) {
    __shared__ float redmax[8];
    __shared__ float redsum[8];
    long row = blockIdx.x;
    float4* p4 = (float4*)(S + row * (long)TT);
    int t = threadIdx.x;                    // 256 threads, 8 floats each
    float4 v0 = p4[t];
    float4 v1 = p4[t + 256];

    float m = fmaxf(fmaxf(fmaxf(v0.x, v0.y), fmaxf(v0.z, v0.w)),
                    fmaxf(fmaxf(v1.x, v1.y), fmaxf(v1.z, v1.w)));
#pragma unroll
    for (int o = 16; o > 0; o >>= 1) m = fmaxf(m, __shfl_xor_sync(0xffffffffu, m, o));
    if ((t & 31) == 0) redmax[t >> 5] = m;
    __syncthreads();
    float rm = redmax[0];
#pragma unroll
    for (int w = 1; w < 8; w++) rm = fmaxf(rm, redmax[w]);

    v0.x = __expf(v0.x - rm); v0.y = __expf(v0.y - rm);
    v0.z = __expf(v0.z - rm); v0.w = __expf(v0.w - rm);
    v1.x = __expf(v1.x - rm); v1.y = __expf(v1.y - rm);
    v1.z = __expf(v1.z - rm); v1.w = __expf(v1.w - rm);

    float s = (v0.x + v0.y) + (v0.z + v0.w) + (v1.x + v1.y) + (v1.z + v1.w);
#pragma unroll
    for (int o = 16; o > 0; o >>= 1) s += __shfl_xor_sync(0xffffffffu, s, o);
    if ((t & 31) == 0) redsum[t >> 5] = s;
    __syncthreads();
    float tot = 0.f;
#pragma unroll
    for (int w = 0; w < 8; w++) tot += redsum[w];
    float inv = 1.0f / tot;

    v0.x *= inv; v0.y *= inv; v0.z *= inv; v0.w *= inv;
    v1.x *= inv; v1.y *= inv; v1.z *= inv; v1.w *= inv;
    p4[t]       = v0;
    p4[t + 256] = v1;
}

// ---------------- bias + relu + partial mean over time -------------------
// grid (D/128, B, 8 splits), 128 threads; each thread owns one output dim.
__global__ void relu_mean_kernel(const float* __restrict__ Z,
                                 const float* __restrict__ bias,
                                 float* __restrict__ Mp) {
    int o  = blockIdx.x * 128 + threadIdx.x;
    int b  = blockIdx.y;
    int sp = blockIdx.z;
    float bo = bias[o];
    const float* p = Z + ((long)b * TT + (long)sp * 256) * DD + o;
    float s = 0.f;
#pragma unroll 8
    for (int i = 0; i < 256; i++) s += fmaxf(p[(long)i * DD] + bo, 0.f);
    Mp[((long)sp * BB + b) * DD + o] = s;
}

// ---------------- classifier: sigmoid(mean . clf_w + clf_b) --------------
__global__ void final_kernel(const float* __restrict__ Mp,
                             const float* __restrict__ clf_w,
                             const float* __restrict__ clf_b,
                             float* __restrict__ out) {
    int b    = threadIdx.x >> 5;   // 8 warps, one per batch row
    int lane = threadIdx.x & 31;
    float s = 0.f;
    for (int o = lane; o < DD; o += 32) {
        float m = 0.f;
#pragma unroll
        for (int sp = 0; sp < 8; sp++) m += Mp[((long)sp * BB + b) * DD + o];
        s += (m * (1.0f / (float)TT)) * clf_w[o];
    }
#pragma unroll
    for (int o = 16; o > 0; o >>= 1) s += __shfl_xor_sync(0xffffffffu, s, o);
    if (lane == 0) out[b] = 1.0f / (1.0f + __expf(-(s + clf_b[0])));
}

// ---------------- launch ---------------------------------------------------
extern "C" void kernel_launch(void* const* d_in, const int* in_sizes, int n_in,
                              void* d_out, int out_size) {
    const int*   x     = (const int*)  d_in[0];
    const float* embed = (const float*)d_in[1];
    const float* W_q   = (const float*)d_in[2];
    const float* W_k   = (const float*)d_in[3];
    const float* W_v   = (const float*)d_in[4];
    const float* lin_w = (const float*)d_in[5];
    const float* lin_b = (const float*)d_in[6];
    const float* clf_w = (const float*)d_in[7];
    const float* clf_b = (const float*)d_in[8];
    float* out = (float*)d_out;

    float *E, *Q, *K, *V, *S, *Y, *Z, *Mp;
    cudaGetSymbolAddress((void**)&E,  g_E);
    cudaGetSymbolAddress((void**)&Q,  g_Q);
    cudaGetSymbolAddress((void**)&K,  g_K);
    cudaGetSymbolAddress((void**)&V,  g_V);
    cudaGetSymbolAddress((void**)&S,  g_S);
    cudaGetSymbolAddress((void**)&Y,  g_Y);
    cudaGetSymbolAddress((void**)&Z,  g_Z);
    cudaGetSymbolAddress((void**)&Mp, g_Mp);

    // 1) E[b,t,:] = embed[x[b,t],:]
    embed_kernel<<<(BB * TT * (DD / 4)) / 256, 256>>>(x, embed, E);

    // 2) Q/K/V[b,t,d] = sum_f E[b,t,f] * W[d,f]   (NT GEMM)
    dim3 gqkv(DD / 128, TT / 128, BB);
    sgemm_kernel<true><<<gqkv, 256>>>(E, W_q, Q, TT, DD, DD, TD, 0, TD, 1.0f);
    sgemm_kernel<true><<<gqkv, 256>>>(E, W_k, K, TT, DD, DD, TD, 0, TD, 1.0f);
    sgemm_kernel<true><<<gqkv, 256>>>(E, W_v, V, TT, DD, DD, TD, 0, TD, 1.0f);

    // 3) S[b,i,j] = SCALE * Q[b,i,:].K[b,j,:]     (NT GEMM)
    dim3 gsc(TT / 128, TT / 128, BB);
    sgemm_kernel<true><<<gsc, 256>>>(Q, K, S, TT, TT, DD, TD, TD, TXT, SCALE);

    // 4) softmax over j
    softmax_kernel<<<BB * TT, 256>>>(S);

    // 5) Y[b,i,d] = sum_j S[b,i,j] * V[b,j,d]     (NN GEMM)
    dim3 gav(DD / 128, TT / 128, BB);
    sgemm_kernel<false><<<gav, 256>>>(S, V, Y, TT, DD, TT, TXT, TD, TD, 1.0f);

    // 6) Z[b,i,o] = Y[b,i,:] . lin_w[o,:]         (NT GEMM, bias in step 7)
    sgemm_kernel<true><<<gav, 256>>>(Y, lin_w, Z, TT, DD, DD, TD, 0, TD, 1.0f);

    // 7) partial mean of relu(Z + b) over time
    relu_mean_kernel<<<dim3(DD / 128, BB, 8), 128>>>(Z, lin_b, Mp);

    // 8) sigmoid classifier
    final_kernel<<<1, 256>>>(Mp, clf_w, clf_b, out);
}

// round 16
// speedup vs baseline: 1.0525x; 1.0029x over previous
#include <cuda_runtime.h>
#include <math.h>

// Problem constants
#define BB   8
#define TT   2048
#define DD   512
#define TD   ((long)TT * DD)       // 1,048,576
#define TXT  ((long)TT * TT)       // 4,194,304
#define SCALE 0.044194173824159216f // 1/sqrt(512)

// ---------------- scratch (static device globals; no runtime allocation) ---
__device__ __align__(128) float g_E[BB * TT * DD];
__device__ __align__(128) float g_Q[BB * TT * DD];
__device__ __align__(128) float g_K[BB * TT * DD];
__device__ __align__(128) float g_V[BB * TT * DD];
__device__ __align__(128) float g_S[(long)BB * TT * TT];
__device__ __align__(128) float g_Y[BB * TT * DD];
__device__ __align__(128) float g_Z[BB * TT * DD];
__device__ __align__(128) float g_Mp[8 * BB * DD];   // [split][b][o]

// ---------------- embedding gather --------------------------------------
__global__ void embed_kernel(const int* __restrict__ x,
                             const float* __restrict__ W,
                             float* __restrict__ E) {
    long i = (long)blockIdx.x * blockDim.x + threadIdx.x;  // float4 units
    int  d4 = (int)(i & 127);            // D/4 = 128
    long bt = i >> 7;
    int tok = __ldg(&x[bt]);
    ((float4*)E)[i] = ((const float4*)W)[(long)tok * 128 + d4];
}

// ---------------- SGEMM: C = alpha * A * op(B) ---------------------------
// A: M x K row-major.  TRANSB: B is N x K row-major (C=A*B^T), else K x N.
// 128x128 block tile, BK=8, 256 threads, 8x8 per-thread microtile,
// one-step register prefetch of the next global tile.
template <bool TRANSB>
__global__ void __launch_bounds__(256)
sgemm_kernel(const float* __restrict__ A, const float* __restrict__ Bm,
             float* __restrict__ C, int M, int N, int K,
             long sA, long sB, long sC, float alpha) {
    __shared__ float As[8][128];
    __shared__ float Bs[8][128];

    const int bz = blockIdx.z;
    A  += (long)bz * sA;
    Bm += (long)bz * sB;
    C  += (long)bz * sC;

    const int m0 = blockIdx.y * 128;
    const int n0 = blockIdx.x * 128;
    const int tid = threadIdx.x;
    const int tx = tid & 15;        // 0..15 -> n microtile
    const int ty = tid >> 4;        // 0..15 -> m microtile

    // A / (NT) B loader indices: one float4 per thread, 128 rows x 8 cols
    const int lrow = tid >> 1;            // 0..127
    const int lcol = (tid & 1) << 2;      // 0 or 4
    // (NN) B loader indices: 8 rows x 128 cols, coalesced
    const int brow = tid >> 5;            // 0..7
    const int bcol = (tid & 31) << 2;     // 0..124

    const float* Aptr = A + (long)(m0 + lrow) * K + lcol;
    const float* Bptr = TRANSB ? (Bm + (long)(n0 + lrow) * K + lcol)
                               : (Bm + (long)brow * N + n0 + bcol);

    float acc[8][8];
#pragma unroll
    for (int i = 0; i < 8; i++)
#pragma unroll
        for (int j = 0; j < 8; j++) acc[i][j] = 0.f;

    // prime the pipeline
    float4 av = *(const float4*)(Aptr);
    float4 bv = TRANSB ? *(const float4*)(Bptr)
                       : *(const float4*)(Bptr);

    for (int k0 = 0; k0 < K; k0 += 8) {
        // stage current tile to smem
        As[lcol + 0][lrow] = av.x;
        As[lcol + 1][lrow] = av.y;
        As[lcol + 2][lrow] = av.z;
        As[lcol + 3][lrow] = av.w;
        if (TRANSB) {
            Bs[lcol + 0][lrow] = bv.x;
            Bs[lcol + 1][lrow] = bv.y;
            Bs[lcol + 2][lrow] = bv.z;
            Bs[lcol + 3][lrow] = bv.w;
        } else {
            *(float4*)&Bs[brow][bcol] = bv;
        }
        __syncthreads();

        // prefetch next global tile (hidden under compute)
        float4 av_n = make_float4(0.f, 0.f, 0.f, 0.f);
        float4 bv_n = make_float4(0.f, 0.f, 0.f, 0.f);
        if (k0 + 8 < K) {
            av_n = *(const float4*)(Aptr + k0 + 8);
            bv_n = TRANSB ? *(const float4*)(Bptr + k0 + 8)
                          : *(const float4*)(Bptr + (long)(k0 + 8) * N);
        }

#pragma unroll
        for (int kk = 0; kk < 8; kk++) {
            float a[8], b[8];
            *(float4*)&a[0] = *(const float4*)&As[kk][ty * 8];
            *(float4*)&a[4] = *(const float4*)&As[kk][ty * 8 + 4];
            *(float4*)&b[0] = *(const float4*)&Bs[kk][tx * 8];
            *(float4*)&b[4] = *(const float4*)&Bs[kk][tx * 8 + 4];
#pragma unroll
            for (int i = 0; i < 8; i++)
#pragma unroll
                for (int j = 0; j < 8; j++)
                    acc[i][j] = fmaf(a[i], b[j], acc[i][j]);
        }
        __syncthreads();
        av = av_n;
        bv = bv_n;
    }

#pragma unroll
    for (int i = 0; i < 8; i++) {
        float* crow = C + (long)(m0 + ty * 8 + i) * N + n0 + tx * 8;
        float4 c0 = make_float4(acc[i][0] * alpha, acc[i][1] * alpha,
                                acc[i][2] * alpha, acc[i][3] * alpha);
        float4 c1 = make_float4(acc[i][4] * alpha, acc[i][5] * alpha,
                                acc[i][6] * alpha, acc[i][7] * alpha);
        *(float4*)crow       = c0;
        *(float4*)(crow + 4) = c1;
    }
}

// ---------------- row softmax over T=2048 --------------------------------
__global__ void softmax_kernel(float* __restrict__ S) {
    __shared__ float redmax[8];
    __shared__ float redsum[8];
    long row = blockIdx.x;
    float4* p4 = (float4*)(S + row * (long)TT);
    int t = threadIdx.x;                    // 256 threads, 8 floats each
    float4 v0 = p4[t];
    float4 v1 = p4[t + 256];

    float m = fmaxf(fmaxf(fmaxf(v0.x, v0.y), fmaxf(v0.z, v0.w)),
                    fmaxf(fmaxf(v1.x, v1.y), fmaxf(v1.z, v1.w)));
#pragma unroll
    for (int o = 16; o > 0; o >>= 1) m = fmaxf(m, __shfl_xor_sync(0xffffffffu, m, o));
    if ((t & 31) == 0) redmax[t >> 5] = m;
    __syncthreads();
    float rm = redmax[0];
#pragma unroll
    for (int w = 1; w < 8; w++) rm = fmaxf(rm, redmax[w]);

    v0.x = __expf(v0.x - rm); v0.y = __expf(v0.y - rm);
    v0.z = __expf(v0.z - rm); v0.w = __expf(v0.w - rm);
    v1.x = __expf(v1.x - rm); v1.y = __expf(v1.y - rm);
    v1.z = __expf(v1.z - rm); v1.w = __expf(v1.w - rm);

    float s = (v0.x + v0.y) + (v0.z + v0.w) + (v1.x + v1.y) + (v1.z + v1.w);
#pragma unroll
    for (int o = 16; o > 0; o >>= 1) s += __shfl_xor_sync(0xffffffffu, s, o);
    if ((t & 31) == 0) redsum[t >> 5] = s;
    __syncthreads();
    float tot = 0.f;
#pragma unroll
    for (int w = 0; w < 8; w++) tot += redsum[w];
    float inv = 1.0f / tot;

    v0.x *= inv; v0.y *= inv; v0.z *= inv; v0.w *= inv;
    v1.x *= inv; v1.y *= inv; v1.z *= inv; v1.w *= inv;
    p4[t]       = v0;
    p4[t + 256] = v1;
}

// ---------------- bias + relu + partial mean over time -------------------
// grid (D/128, B, 8 splits), 128 threads; each thread owns one output dim.
__global__ void relu_mean_kernel(const float* __restrict__ Z,
                                 const float* __restrict__ bias,
                                 float* __restrict__ Mp) {
    int o  = blockIdx.x * 128 + threadIdx.x;
    int b  = blockIdx.y;
    int sp = blockIdx.z;
    float bo = bias[o];
    const float* p = Z + ((long)b * TT + (long)sp * 256) * DD + o;
    float s = 0.f;
#pragma unroll 8
    for (int i = 0; i < 256; i++) s += fmaxf(p[(long)i * DD] + bo, 0.f);
    Mp[((long)sp * BB + b) * DD + o] = s;
}

// ---------------- classifier: sigmoid(mean . clf_w + clf_b) --------------
__global__ void final_kernel(const float* __restrict__ Mp,
                             const float* __restrict__ clf_w,
                             const float* __restrict__ clf_b,
                             float* __restrict__ out) {
    int b    = threadIdx.x >> 5;   // 8 warps, one per batch row
    int lane = threadIdx.x & 31;
    float s = 0.f;
    for (int o = lane; o < DD; o += 32) {
        float m = 0.f;
#pragma unroll
        for (int sp = 0; sp < 8; sp++) m += Mp[((long)sp * BB + b) * DD + o];
        s += (m * (1.0f / (float)TT)) * clf_w[o];
    }
#pragma unroll
    for (int o = 16; o > 0; o >>= 1) s += __shfl_xor_sync(0xffffffffu, s, o);
    if (lane == 0) out[b] = 1.0f / (1.0f + __expf(-(s + clf_b[0])));
}

// ---------------- launch ---------------------------------------------------
extern "C" void kernel_launch(void* const* d_in, const int* in_sizes, int n_in,
                              void* d_out, int out_size) {
    const int*   x     = (const int*)  d_in[0];
    const float* embed = (const float*)d_in[1];
    const float* W_q   = (const float*)d_in[2];
    const float* W_k   = (const float*)d_in[3];
    const float* W_v   = (const float*)d_in[4];
    const float* lin_w = (const float*)d_in[5];
    const float* lin_b = (const float*)d_in[6];
    const float* clf_w = (const float*)d_in[7];
    const float* clf_b = (const float*)d_in[8];
    float* out = (float*)d_out;

    float *E, *Q, *K, *V, *S, *Y, *Z, *Mp;
    cudaGetSymbolAddress((void**)&E,  g_E);
    cudaGetSymbolAddress((void**)&Q,  g_Q);
    cudaGetSymbolAddress((void**)&K,  g_K);
    cudaGetSymbolAddress((void**)&V,  g_V);
    cudaGetSymbolAddress((void**)&S,  g_S);
    cudaGetSymbolAddress((void**)&Y,  g_Y);
    cudaGetSymbolAddress((void**)&Z,  g_Z);
    cudaGetSymbolAddress((void**)&Mp, g_Mp);

    // 1) E[b,t,:] = embed[x[b,t],:]
    embed_kernel<<<(BB * TT * (DD / 4)) / 256, 256>>>(x, embed, E);

    // 2) Q/K/V[b,t,d] = sum_f E[b,t,f] * W[d,f]   (NT GEMM)
    dim3 gqkv(DD / 128, TT / 128, BB);
    sgemm_kernel<true><<<gqkv, 256>>>(E, W_q, Q, TT, DD, DD, TD, 0, TD, 1.0f);
    sgemm_kernel<true><<<gqkv, 256>>>(E, W_k, K, TT, DD, DD, TD, 0, TD, 1.0f);
    sgemm_kernel<true><<<gqkv, 256>>>(E, W_v, V, TT, DD, DD, TD, 0, TD, 1.0f);

    // 3) S[b,i,j] = SCALE * Q[b,i,:].K[b,j,:]     (NT GEMM)
    dim3 gsc(TT / 128, TT / 128, BB);
    sgemm_kernel<true><<<gsc, 256>>>(Q, K, S, TT, TT, DD, TD, TD, TXT, SCALE);

    // 4) softmax over j
    softmax_kernel<<<BB * TT, 256>>>(S);

    // 5) Y[b,i,d] = sum_j S[b,i,j] * V[b,j,d]     (NN GEMM)
    dim3 gav(DD / 128, TT / 128, BB);
    sgemm_kernel<false><<<gav, 256>>>(S, V, Y, TT, DD, TT, TXT, TD, TD, 1.0f);

    // 6) Z[b,i,o] = Y[b,i,:] . lin_w[o,:]         (NT GEMM, bias in step 7)
    sgemm_kernel<true><<<gav, 256>>>(Y, lin_w, Z, TT, DD, DD, TD, 0, TD, 1.0f);

    // 7) partial mean of relu(Z + b) over time
    relu_mean_kernel<<<dim3(DD / 128, BB, 8), 128>>>(Z, lin_b, Mp);

    // 8) sigmoid classifier
    final_kernel<<<1, 256>>>(Mp, clf_w, clf_b, out);
}